// round 7
// baseline (speedup 1.0000x reference)
#include <cuda_runtime.h>
#include <cuda_bf16.h>
#include <cstdint>

// out[b,n] = max(0, 1 - sum_k (1 - xs[b,k]) * sigmoid(W[k,n]))
// B=4096, K=1024, N=1024, fp32 in/out.
// Single fused kernel: in-kernel prep (fp32 -> bf16, tiled+SW128) published
// per 16KB block via release flags; GEMM pipeline consumes blocks as ready.
static constexpr int Bdim = 4096;
static constexpr int Kdim = 1024;
static constexpr int Ndim = 1024;

// Tiled, pre-swizzled operand storage (__device__ globals: allocation-free rule).
// g_A: blocks i = mt*16+kt (mt 0..31, kt 0..15): 128 rows x 64 k bf16,
//      128B rows, SW128, 16KB contiguous.
// g_W: blocks j = nt*16+kt (nt 0..7): two 8KB halves (n 0..63 / 64..127),
//      each 64 k-rows x 64 n bf16, 128B rows, SW128.
__device__ __align__(128) __nv_bfloat16 g_A[(size_t)Bdim * Kdim];
__device__ __align__(128) __nv_bfloat16 g_W[(size_t)Kdim * Ndim];

// Producer->consumer block-ready flags (zero-initialized) + replay epoch ticket.
__device__ uint32_t g_flagA[512];
__device__ uint32_t g_flagW[128];
__device__ unsigned long long g_ticket;

__device__ __forceinline__ uint32_t swz(uint32_t x) { return x ^ ((x >> 3) & 0x70); }

__device__ __forceinline__ uint32_t ld_acq(const uint32_t* p) {
    uint32_t v;
    asm volatile("ld.acquire.gpu.global.b32 %0, [%1];" : "=r"(v) : "l"(p) : "memory");
    return v;
}
__device__ __forceinline__ void st_rel(uint32_t* p, uint32_t v) {
    asm volatile("st.release.gpu.global.b32 [%0], %1;" :: "l"(p), "r"(v) : "memory");
}

__device__ __forceinline__ void mbar_wait(uint32_t addr, uint32_t parity) {
    asm volatile(
        "{\n\t.reg .pred P;\n"
        "W_%=:\n\t"
        "mbarrier.try_wait.parity.acquire.cta.shared::cta.b64 P, [%0], %1, 0x989680;\n\t"
        "@P bra.uni D_%=;\n\t"
        "bra.uni W_%=;\n"
        "D_%=:\n\t}"
        :: "r"(addr), "r"(parity) : "memory");
}

static constexpr int STAGES = 3;
static constexpr int KT = Kdim / 64;                 // 16
static constexpr uint32_t STAGE_B = 32768;           // 16KB A + 16KB B
static constexpr uint32_t BUF_OFF = 128;
static constexpr uint32_t SMEM_BYTES = BUF_OFF + STAGES * STAGE_B;  // 98432

__global__ __launch_bounds__(256, 2)
void fuzzyand_fused(const float* __restrict__ xs, const float* __restrict__ w,
                    float* __restrict__ out) {
    extern __shared__ char smem[];
    const uint32_t sb = (uint32_t)__cvta_generic_to_shared(smem);
    const int tid = threadIdx.x;
    const int wid = tid >> 5;
    const int lane = tid & 31;
    const int wm = (wid & 3) * 32;
    const int wn = (wid >> 2) * 64;
    const int bm = blockIdx.y * 128;
    const int bn = blockIdx.x * 128;
    const int cta = blockIdx.y * 8 + blockIdx.x;     // 0..255

    // ---- epoch + mbarrier init (tid 0) ----
    __shared__ uint32_t s_target;
    if (tid == 0) {
        unsigned long long t = atomicAdd(&g_ticket, 1ULL);
        s_target = (uint32_t)(t >> 8) + 1u;          // grid = 256 CTAs
#pragma unroll
        for (int s = 0; s < STAGES; s++)
            asm volatile("mbarrier.init.shared.b64 [%0], %1;"
                         :: "r"(sb + 8 * s), "r"(1u) : "memory");
    }

    // =======================================================================
    // Phase 1: produce this CTA's blocks (unconditional -> deadlock-free).
    // A blocks 2*cta, 2*cta+1; W block cta if cta < 128.
    // =======================================================================
    char* gA = reinterpret_cast<char*>(g_A);
    char* gW = reinterpret_cast<char*>(g_W);

#pragma unroll
    for (int bi = 0; bi < 2; bi++) {
        const int i = 2 * cta + bi;
        const int mt = i >> 4, kt = i & 15;
        const float* srcb = xs + (size_t)mt * 128 * 1024 + kt * 64;
        char* dstb = gA + (size_t)i * 16384;
        float4 v[8];
        uint32_t doff[4];
#pragma unroll
        for (int q = 0; q < 4; q++) {                // MLP=8 loads batched
            int ch = tid + q * 256;
            int r = ch >> 3, c8 = ch & 7;
            const float4* s4 = reinterpret_cast<const float4*>(srcb + ((size_t)r * 1024 + c8 * 8) * 4);
            v[2 * q] = s4[0];
            v[2 * q + 1] = s4[1];
            doff[q] = swz((uint32_t)(r * 128 + c8 * 16));
        }
#pragma unroll
        for (int q = 0; q < 4; q++) {
            __nv_bfloat162 p0 = __floats2bfloat162_rn(1.f - v[2 * q].x, 1.f - v[2 * q].y);
            __nv_bfloat162 p1 = __floats2bfloat162_rn(1.f - v[2 * q].z, 1.f - v[2 * q].w);
            __nv_bfloat162 p2 = __floats2bfloat162_rn(1.f - v[2 * q + 1].x, 1.f - v[2 * q + 1].y);
            __nv_bfloat162 p3 = __floats2bfloat162_rn(1.f - v[2 * q + 1].z, 1.f - v[2 * q + 1].w);
            uint4 u;
            u.x = *reinterpret_cast<uint32_t*>(&p0);
            u.y = *reinterpret_cast<uint32_t*>(&p1);
            u.z = *reinterpret_cast<uint32_t*>(&p2);
            u.w = *reinterpret_cast<uint32_t*>(&p3);
            *reinterpret_cast<uint4*>(dstb + doff[q]) = u;
        }
    }

    if (cta < 128) {
        const int j = cta;
        const int nt = j >> 4, kt = j & 15;
        char* dstb = gW + (size_t)j * 16384;
        float4 v[8];
        uint32_t doff[4];
#pragma unroll
        for (int q = 0; q < 4; q++) {
            int ch = tid + q * 256;                   // 0..1023
            int h = ch >> 9, rem = ch & 511;
            int kl = rem >> 3, nl8 = rem & 7;
            const float4* s4 = reinterpret_cast<const float4*>(
                w + (size_t)(kt * 64 + kl) * 1024 + nt * 128 + h * 64 + nl8 * 8);
            v[2 * q] = s4[0];
            v[2 * q + 1] = s4[1];
            doff[q] = (uint32_t)(h * 8192) + swz((uint32_t)(kl * 128 + nl8 * 16));
        }
#pragma unroll
        for (int q = 0; q < 4; q++) {
            float s0 = 1.0f / (1.0f + __expf(-v[2 * q].x));
            float s1 = 1.0f / (1.0f + __expf(-v[2 * q].y));
            float s2 = 1.0f / (1.0f + __expf(-v[2 * q].z));
            float s3 = 1.0f / (1.0f + __expf(-v[2 * q].w));
            float s4f = 1.0f / (1.0f + __expf(-v[2 * q + 1].x));
            float s5 = 1.0f / (1.0f + __expf(-v[2 * q + 1].y));
            float s6 = 1.0f / (1.0f + __expf(-v[2 * q + 1].z));
            float s7 = 1.0f / (1.0f + __expf(-v[2 * q + 1].w));
            __nv_bfloat162 p0 = __floats2bfloat162_rn(s0, s1);
            __nv_bfloat162 p1 = __floats2bfloat162_rn(s2, s3);
            __nv_bfloat162 p2 = __floats2bfloat162_rn(s4f, s5);
            __nv_bfloat162 p3 = __floats2bfloat162_rn(s6, s7);
            uint4 u;
            u.x = *reinterpret_cast<uint32_t*>(&p0);
            u.y = *reinterpret_cast<uint32_t*>(&p1);
            u.z = *reinterpret_cast<uint32_t*>(&p2);
            u.w = *reinterpret_cast<uint32_t*>(&p3);
            *reinterpret_cast<uint4*>(dstb + doff[q]) = u;
        }
    }

    __syncthreads();                                  // CTA's stores done
    const uint32_t target = s_target;
    if (tid == 0) {
        st_rel(&g_flagA[2 * cta], target);
        st_rel(&g_flagA[2 * cta + 1], target);
        if (cta < 128) st_rel(&g_flagW[cta], target);
    }

    // =======================================================================
    // Phase 2: GEMM (R3 winner), gated per-kt by block-ready flags.
    // =======================================================================
    const char* Ab = reinterpret_cast<const char*>(g_A) + (size_t)(blockIdx.y * 16) * 16384;
    const char* Bb = reinterpret_cast<const char*>(g_W) + (size_t)(blockIdx.x * 16) * 16384;

    auto wait_kt = [&](int kt) {
        const uint32_t* fa = &g_flagA[blockIdx.y * 16 + kt];
        const uint32_t* fw = &g_flagW[blockIdx.x * 16 + kt];
        while (ld_acq(fa) != target) {}
        while (ld_acq(fw) != target) {}
        asm volatile("fence.proxy.async;" ::: "memory");
    };

    auto issue = [&](int stage, int kt) {
        uint32_t mb = sb + 8 * stage;
        uint32_t dst = sb + BUF_OFF + stage * STAGE_B;
        asm volatile("mbarrier.arrive.expect_tx.shared.b64 _, [%0], %1;"
                     :: "r"(mb), "r"(STAGE_B) : "memory");
        asm volatile(
            "cp.async.bulk.shared::cluster.global.mbarrier::complete_tx::bytes "
            "[%0], [%1], %2, [%3];"
            :: "r"(dst), "l"(Ab + (size_t)kt * 16384), "r"(16384u), "r"(mb) : "memory");
        asm volatile(
            "cp.async.bulk.shared::cluster.global.mbarrier::complete_tx::bytes "
            "[%0], [%1], %2, [%3];"
            :: "r"(dst + 16384u), "l"(Bb + (size_t)kt * 16384), "r"(16384u), "r"(mb) : "memory");
    };

    if (tid == 0) {
        wait_kt(0); issue(0, 0);
        wait_kt(1); issue(1, 1);
    }

    float acc[2][8][4];
#pragma unroll
    for (int mi = 0; mi < 2; mi++)
#pragma unroll
        for (int ni = 0; ni < 8; ni++)
#pragma unroll
            for (int e = 0; e < 4; e++) acc[mi][ni][e] = 0.0f;

    const uint32_t a_row0 = (uint32_t)(wm + (lane & 15)) * 128;
    const uint32_t a_xor0 = ((wm + (lane & 15)) & 7) << 4;
    const uint32_t a_row1 = (uint32_t)(wm + 16 + (lane & 15)) * 128;
    const uint32_t a_xor1 = ((wm + 16 + (lane & 15)) & 7) << 4;
    const uint32_t a_hi = (uint32_t)((lane >> 4) << 4);
    const uint32_t b_half = (uint32_t)((wn >> 6) * 8192);
    const uint32_t b_nb = (uint32_t)((wn & 63) * 2 + ((lane >> 4) << 4));

#pragma unroll 1
    for (int kt = 0; kt < KT; kt++) {
        const int stage = kt % STAGES;
        mbar_wait(sb + 8 * stage, (uint32_t)((kt / STAGES) & 1));

        const uint32_t a_s = sb + BUF_OFF + stage * STAGE_B;
        const uint32_t b_s = a_s + 16384;

#pragma unroll
        for (int ks = 0; ks < 4; ks++) {
            const uint32_t kb = ks * 32;

            uint32_t a[2][4];
            {
                uint32_t bc = kb + a_hi;
                uint32_t ad0 = a_s + ((a_row0 + bc) ^ a_xor0);
                uint32_t ad1 = a_s + ((a_row1 + bc) ^ a_xor1);
                asm volatile(
                    "ldmatrix.sync.aligned.m8n8.x4.shared.b16 {%0,%1,%2,%3}, [%4];"
                    : "=r"(a[0][0]), "=r"(a[0][1]), "=r"(a[0][2]), "=r"(a[0][3])
                    : "r"(ad0));
                asm volatile(
                    "ldmatrix.sync.aligned.m8n8.x4.shared.b16 {%0,%1,%2,%3}, [%4];"
                    : "=r"(a[1][0]), "=r"(a[1][1]), "=r"(a[1][2]), "=r"(a[1][3])
                    : "r"(ad1));
            }

            uint32_t b[8][2];
            {
                uint32_t krow = (uint32_t)(ks * 16 + (lane & 15));
                uint32_t base = krow * 128;
                uint32_t kxor = (krow & 7) << 4;
#pragma unroll
                for (int nc = 0; nc < 4; nc++) {
                    uint32_t bc = b_nb + nc * 32;
                    uint32_t ad = b_s + b_half + ((base + bc) ^ kxor);
                    asm volatile(
                        "ldmatrix.sync.aligned.m8n8.x4.trans.shared.b16 {%0,%1,%2,%3}, [%4];"
                        : "=r"(b[2 * nc][0]), "=r"(b[2 * nc][1]),
                          "=r"(b[2 * nc + 1][0]), "=r"(b[2 * nc + 1][1])
                        : "r"(ad));
                }
            }

#pragma unroll
            for (int mi = 0; mi < 2; mi++)
#pragma unroll
                for (int ni = 0; ni < 8; ni++) {
                    asm volatile(
                        "mma.sync.aligned.m16n8k16.row.col.f32.bf16.bf16.f32 "
                        "{%0,%1,%2,%3}, {%4,%5,%6,%7}, {%8,%9}, {%0,%1,%2,%3};"
                        : "+f"(acc[mi][ni][0]), "+f"(acc[mi][ni][1]),
                          "+f"(acc[mi][ni][2]), "+f"(acc[mi][ni][3])
                        : "r"(a[mi][0]), "r"(a[mi][1]), "r"(a[mi][2]), "r"(a[mi][3]),
                          "r"(b[ni][0]), "r"(b[ni][1]));
                }
        }

        __syncthreads();
        if (tid == 0 && kt + 2 < KT) { wait_kt(kt + 2); issue((kt + 2) % STAGES, kt + 2); }
    }

    float* outp = out + (size_t)bm * Ndim + bn;
#pragma unroll
    for (int mi = 0; mi < 2; mi++) {
#pragma unroll
        for (int ni = 0; ni < 8; ni++) {
            int r0 = wm + mi * 16 + (lane >> 2);
            int c0 = wn + ni * 8 + (lane & 3) * 2;
            float2 v0, v1;
            v0.x = fmaxf(0.0f, 1.0f - acc[mi][ni][0]);
            v0.y = fmaxf(0.0f, 1.0f - acc[mi][ni][1]);
            v1.x = fmaxf(0.0f, 1.0f - acc[mi][ni][2]);
            v1.y = fmaxf(0.0f, 1.0f - acc[mi][ni][3]);
            *reinterpret_cast<float2*>(&outp[(size_t)r0 * Ndim + c0])       = v0;
            *reinterpret_cast<float2*>(&outp[(size_t)(r0 + 8) * Ndim + c0]) = v1;
        }
    }
}

// ---------------------------------------------------------------------------
extern "C" void kernel_launch(void* const* d_in, const int* in_sizes, int n_in,
                              void* d_out, int out_size) {
    const float* xs = (const float*)d_in[0];   // [4096,1024] fp32
    const float* w  = (const float*)d_in[1];   // [1024,1024] fp32
    float* out = (float*)d_out;
    (void)in_sizes; (void)n_in; (void)out_size;

    cudaFuncSetAttribute(fuzzyand_fused,
                         cudaFuncAttributeMaxDynamicSharedMemorySize, SMEM_BYTES);
    dim3 grid(Ndim / 128, Bdim / 128);  // (8, 32) = 256 CTAs, all co-resident
    fuzzyand_fused<<<grid, 256, SMEM_BYTES>>>(xs, w, out);
}

// round 8
// speedup vs baseline: 1.1615x; 1.1615x over previous
#include <cuda_runtime.h>
#include <cuda_bf16.h>
#include <cstdint>

// out[b,n] = max(0, 1 - sum_k (1 - xs[b,k]) * sigmoid(W[k,n]))
// B=4096, K=1024, N=1024, fp32 in/out.
// W prepped (sigmoid->bf16, tiled+SW128) by a tiny kernel; A converted
// INSIDE the GEMM (LDG fp32 -> cvt -> STS bf16, 2 k-tiles ahead).
static constexpr int Bdim = 4096;
static constexpr int Kdim = 1024;
static constexpr int Ndim = 1024;

// g_W blocks j = nt*16+kt (nt 0..7, kt 0..15): two 8KB halves (n 0..63 / 64..127),
// each 64 k-rows x 64 n bf16, 128B rows, SW128. 16KB per block.
__device__ __align__(128) __nv_bfloat16 g_W[(size_t)Kdim * Ndim];

__device__ __forceinline__ uint32_t swz(uint32_t x) { return x ^ ((x >> 3) & 0x70); }

// ---------------------------------------------------------------------------
// prep_W: sigmoid -> bf16, tiled + SW128. 128 blocks x 256 threads x 4 chunks.
// ---------------------------------------------------------------------------
__global__ __launch_bounds__(256) void prep_W_kernel(const float* __restrict__ w) {
    const int tid = threadIdx.x;
    const int j = blockIdx.x;                 // block id = nt*16+kt
    const int nt = j >> 4, kt = j & 15;
    char* dstb = reinterpret_cast<char*>(g_W) + (size_t)j * 16384;

    float4 v[8];
    uint32_t doff[4];
#pragma unroll
    for (int q = 0; q < 4; q++) {
        int ch = tid + q * 256;               // 0..1023 16B chunks
        int h = ch >> 9, rem = ch & 511;
        int kl = rem >> 3, nl8 = rem & 7;
        const float4* s4 = reinterpret_cast<const float4*>(
            w + (size_t)(kt * 64 + kl) * 1024 + nt * 128 + h * 64 + nl8 * 8);
        v[2 * q] = s4[0];
        v[2 * q + 1] = s4[1];
        doff[q] = (uint32_t)(h * 8192) + swz((uint32_t)(kl * 128 + nl8 * 16));
    }
#pragma unroll
    for (int q = 0; q < 4; q++) {
        float s0 = 1.0f / (1.0f + __expf(-v[2 * q].x));
        float s1 = 1.0f / (1.0f + __expf(-v[2 * q].y));
        float s2 = 1.0f / (1.0f + __expf(-v[2 * q].z));
        float s3 = 1.0f / (1.0f + __expf(-v[2 * q].w));
        float s4f = 1.0f / (1.0f + __expf(-v[2 * q + 1].x));
        float s5 = 1.0f / (1.0f + __expf(-v[2 * q + 1].y));
        float s6 = 1.0f / (1.0f + __expf(-v[2 * q + 1].z));
        float s7 = 1.0f / (1.0f + __expf(-v[2 * q + 1].w));
        __nv_bfloat162 p0 = __floats2bfloat162_rn(s0, s1);
        __nv_bfloat162 p1 = __floats2bfloat162_rn(s2, s3);
        __nv_bfloat162 p2 = __floats2bfloat162_rn(s4f, s5);
        __nv_bfloat162 p3 = __floats2bfloat162_rn(s6, s7);
        uint4 u;
        u.x = *reinterpret_cast<uint32_t*>(&p0);
        u.y = *reinterpret_cast<uint32_t*>(&p1);
        u.z = *reinterpret_cast<uint32_t*>(&p2);
        u.w = *reinterpret_cast<uint32_t*>(&p3);
        *reinterpret_cast<uint4*>(dstb + doff[q]) = u;
    }
}

// ---------------------------------------------------------------------------
// GEMM with in-kernel A conversion.
// smem: [0,24) mbars; A stages 3x16KB at A_OFF; B stages 3x16KB at B_OFF.
// ---------------------------------------------------------------------------
static constexpr int STAGES = 3;
static constexpr int KT = Kdim / 64;                 // 16
static constexpr uint32_t A_OFF = 128;
static constexpr uint32_t B_OFF = A_OFF + 3 * 16384;
static constexpr uint32_t SMEM_BYTES = B_OFF + 3 * 16384;   // 98432

__device__ __forceinline__ void mbar_wait(uint32_t addr, uint32_t parity) {
    asm volatile(
        "{\n\t.reg .pred P;\n"
        "W_%=:\n\t"
        "mbarrier.try_wait.parity.acquire.cta.shared::cta.b64 P, [%0], %1, 0x989680;\n\t"
        "@P bra.uni D_%=;\n\t"
        "bra.uni W_%=;\n"
        "D_%=:\n\t}"
        :: "r"(addr), "r"(parity) : "memory");
}

__device__ __forceinline__ void sts128(uint32_t addr, uint32_t x, uint32_t y,
                                       uint32_t z, uint32_t w) {
    asm volatile("st.shared.v4.b32 [%0], {%1,%2,%3,%4};"
                 :: "r"(addr), "r"(x), "r"(y), "r"(z), "r"(w) : "memory");
}

__device__ __forceinline__ uint4 cvtA(const float4& v0, const float4& v1) {
    __nv_bfloat162 p0 = __floats2bfloat162_rn(1.f - v0.x, 1.f - v0.y);
    __nv_bfloat162 p1 = __floats2bfloat162_rn(1.f - v0.z, 1.f - v0.w);
    __nv_bfloat162 p2 = __floats2bfloat162_rn(1.f - v1.x, 1.f - v1.y);
    __nv_bfloat162 p3 = __floats2bfloat162_rn(1.f - v1.z, 1.f - v1.w);
    uint4 u;
    u.x = *reinterpret_cast<uint32_t*>(&p0);
    u.y = *reinterpret_cast<uint32_t*>(&p1);
    u.z = *reinterpret_cast<uint32_t*>(&p2);
    u.w = *reinterpret_cast<uint32_t*>(&p3);
    return u;
}

__global__ __launch_bounds__(256, 2)
void fuzzyand_gemm(const float* __restrict__ xs, float* __restrict__ out) {
    extern __shared__ char smem[];
    const uint32_t sb = (uint32_t)__cvta_generic_to_shared(smem);
    const int tid = threadIdx.x;
    const int wid = tid >> 5;
    const int lane = tid & 31;
    const int wm = (wid & 3) * 32;
    const int wn = (wid >> 2) * 64;
    const int bm = blockIdx.y * 128;
    const int bn = blockIdx.x * 128;

    if (tid == 0) {
#pragma unroll
        for (int s = 0; s < STAGES; s++)
            asm volatile("mbarrier.init.shared.b64 [%0], %1;"
                         :: "r"(sb + 8 * s), "r"(1u) : "memory");
    }
    __syncthreads();

    const char* Bb = reinterpret_cast<const char*>(g_W) + (size_t)(blockIdx.x * 16) * 16384;

    auto issueB = [&](int stage, int kt) {
        uint32_t mb = sb + 8 * stage;
        asm volatile("mbarrier.arrive.expect_tx.shared.b64 _, [%0], %1;"
                     :: "r"(mb), "r"(16384u) : "memory");
        asm volatile(
            "cp.async.bulk.shared::cluster.global.mbarrier::complete_tx::bytes "
            "[%0], [%1], %2, [%3];"
            :: "r"(sb + B_OFF + stage * 16384), "l"(Bb + (size_t)kt * 16384),
               "r"(16384u), "r"(mb) : "memory");
    };

    if (tid == 0) { issueB(0, 0); issueB(1, 1); }

    // A-tile producer: thread tid handles chunk ch (0..1023):
    //   r = ch>>3 (row), c8 = ch&7 (8-k group); src 2xfloat4; dst swz(r*128+c8*16).
    const float* xrow = xs;                    // xs[(bm+r)*1024 + kt*64 + c8*8]
    auto srcA = [&](int kt, int ch) {
        int r = ch >> 3, c8 = ch & 7;
        return reinterpret_cast<const float4*>(
            xs + (size_t)(bm + r) * 1024 + kt * 64 + c8 * 8);
    };
    auto dstA = [&](int stage, int ch) {
        int r = ch >> 3, c8 = ch & 7;
        return sb + A_OFF + stage * 16384 + swz((uint32_t)(r * 128 + c8 * 16));
    };
    (void)xrow;

    // Prologue: convert A for kt=0 (stage 0) and kt=1 (stage 1).
#pragma unroll
    for (int kt = 0; kt < 2; kt++) {
        float4 v[8];
#pragma unroll
        for (int q = 0; q < 4; q++) {
            const float4* s4 = srcA(kt, tid + q * 256);
            v[2 * q] = s4[0];
            v[2 * q + 1] = s4[1];
        }
#pragma unroll
        for (int q = 0; q < 4; q++) {
            uint4 u = cvtA(v[2 * q], v[2 * q + 1]);
            sts128(dstA(kt, tid + q * 256), u.x, u.y, u.z, u.w);
        }
    }
    __syncthreads();

    float acc[2][8][4];
#pragma unroll
    for (int mi = 0; mi < 2; mi++)
#pragma unroll
        for (int ni = 0; ni < 8; ni++)
#pragma unroll
            for (int e = 0; e < 4; e++) acc[mi][ni][e] = 0.0f;

    const uint32_t a_row0 = (uint32_t)(wm + (lane & 15)) * 128;
    const uint32_t a_xor0 = ((wm + (lane & 15)) & 7) << 4;
    const uint32_t a_row1 = (uint32_t)(wm + 16 + (lane & 15)) * 128;
    const uint32_t a_xor1 = ((wm + 16 + (lane & 15)) & 7) << 4;
    const uint32_t a_hi = (uint32_t)((lane >> 4) << 4);
    const uint32_t b_half = (uint32_t)((wn >> 6) * 8192);
    const uint32_t b_nb = (uint32_t)((wn & 63) * 2 + ((lane >> 4) << 4));

#pragma unroll 1
    for (int kt = 0; kt < KT; kt++) {
        const int stage = kt % STAGES;
        const int pstage = (kt + 2) % STAGES;
        const bool produce = (kt + 2 < KT);

        mbar_wait(sb + 8 * stage, (uint32_t)((kt / STAGES) & 1));

        const uint32_t a_s = sb + A_OFF + stage * 16384;
        const uint32_t b_s = sb + B_OFF + stage * 16384;

        // A producer, half-batch 1: LDG issued before MMAs (latency hidden).
        float4 pv[4];
        if (produce) {
#pragma unroll
            for (int q = 0; q < 2; q++) {
                const float4* s4 = srcA(kt + 2, tid + q * 256);
                pv[2 * q] = s4[0];
                pv[2 * q + 1] = s4[1];
            }
        }

#pragma unroll
        for (int ks = 0; ks < 4; ks++) {
            const uint32_t kb = ks * 32;

            uint32_t a[2][4];
            {
                uint32_t bc = kb + a_hi;
                uint32_t ad0 = a_s + ((a_row0 + bc) ^ a_xor0);
                uint32_t ad1 = a_s + ((a_row1 + bc) ^ a_xor1);
                asm volatile(
                    "ldmatrix.sync.aligned.m8n8.x4.shared.b16 {%0,%1,%2,%3}, [%4];"
                    : "=r"(a[0][0]), "=r"(a[0][1]), "=r"(a[0][2]), "=r"(a[0][3])
                    : "r"(ad0));
                asm volatile(
                    "ldmatrix.sync.aligned.m8n8.x4.shared.b16 {%0,%1,%2,%3}, [%4];"
                    : "=r"(a[1][0]), "=r"(a[1][1]), "=r"(a[1][2]), "=r"(a[1][3])
                    : "r"(ad1));
            }

            uint32_t b[8][2];
            {
                uint32_t krow = (uint32_t)(ks * 16 + (lane & 15));
                uint32_t base = krow * 128;
                uint32_t kxor = (krow & 7) << 4;
#pragma unroll
                for (int nc = 0; nc < 4; nc++) {
                    uint32_t bc = b_nb + nc * 32;
                    uint32_t ad = b_s + b_half + ((base + bc) ^ kxor);
                    asm volatile(
                        "ldmatrix.sync.aligned.m8n8.x4.trans.shared.b16 {%0,%1,%2,%3}, [%4];"
                        : "=r"(b[2 * nc][0]), "=r"(b[2 * nc][1]),
                          "=r"(b[2 * nc + 1][0]), "=r"(b[2 * nc + 1][1])
                        : "r"(ad));
                }
            }

#pragma unroll
            for (int mi = 0; mi < 2; mi++)
#pragma unroll
                for (int ni = 0; ni < 8; ni++) {
                    asm volatile(
                        "mma.sync.aligned.m16n8k16.row.col.f32.bf16.bf16.f32 "
                        "{%0,%1,%2,%3}, {%4,%5,%6,%7}, {%8,%9}, {%0,%1,%2,%3};"
                        : "+f"(acc[mi][ni][0]), "+f"(acc[mi][ni][1]),
                          "+f"(acc[mi][ni][2]), "+f"(acc[mi][ni][3])
                        : "r"(a[mi][0]), "r"(a[mi][1]), "r"(a[mi][2]), "r"(a[mi][3]),
                          "r"(b[ni][0]), "r"(b[ni][1]));
                }

            // interleave A-producer work between MMA groups
            if (ks == 1 && produce) {
                // store half-batch 1, load half-batch 2 (reuse pv after stores)
                uint4 u0 = cvtA(pv[0], pv[1]);
                uint4 u1 = cvtA(pv[2], pv[3]);
                sts128(dstA(pstage, tid), u0.x, u0.y, u0.z, u0.w);
                sts128(dstA(pstage, tid + 256), u1.x, u1.y, u1.z, u1.w);
#pragma unroll
                for (int q = 0; q < 2; q++) {
                    const float4* s4 = srcA(kt + 2, tid + (q + 2) * 256);
                    pv[2 * q] = s4[0];
                    pv[2 * q + 1] = s4[1];
                }
            }
            if (ks == 3 && produce) {
                uint4 u0 = cvtA(pv[0], pv[1]);
                uint4 u1 = cvtA(pv[2], pv[3]);
                sts128(dstA(pstage, tid + 512), u0.x, u0.y, u0.z, u0.w);
                sts128(dstA(pstage, tid + 768), u1.x, u1.y, u1.z, u1.w);
            }
        }

        __syncthreads();   // A(kt+2) visible; all warps done with stage kt
        if (tid == 0 && kt + 2 < KT) issueB((kt + 2) % STAGES, kt + 2);
    }

    float* outp = out + (size_t)bm * Ndim + bn;
#pragma unroll
    for (int mi = 0; mi < 2; mi++) {
#pragma unroll
        for (int ni = 0; ni < 8; ni++) {
            int r0 = wm + mi * 16 + (lane >> 2);
            int c0 = wn + ni * 8 + (lane & 3) * 2;
            float2 v0, v1;
            v0.x = fmaxf(0.0f, 1.0f - acc[mi][ni][0]);
            v0.y = fmaxf(0.0f, 1.0f - acc[mi][ni][1]);
            v1.x = fmaxf(0.0f, 1.0f - acc[mi][ni][2]);
            v1.y = fmaxf(0.0f, 1.0f - acc[mi][ni][3]);
            *reinterpret_cast<float2*>(&outp[(size_t)r0 * Ndim + c0])       = v0;
            *reinterpret_cast<float2*>(&outp[(size_t)(r0 + 8) * Ndim + c0]) = v1;
        }
    }
}

// ---------------------------------------------------------------------------
extern "C" void kernel_launch(void* const* d_in, const int* in_sizes, int n_in,
                              void* d_out, int out_size) {
    const float* xs = (const float*)d_in[0];   // [4096,1024] fp32
    const float* w  = (const float*)d_in[1];   // [1024,1024] fp32
    float* out = (float*)d_out;
    (void)in_sizes; (void)n_in; (void)out_size;

    prep_W_kernel<<<128, 256>>>(w);

    cudaFuncSetAttribute(fuzzyand_gemm,
                         cudaFuncAttributeMaxDynamicSharedMemorySize, SMEM_BYTES);
    dim3 grid(Ndim / 128, Bdim / 128);  // (8, 32) = 256 CTAs
    fuzzyand_gemm<<<grid, 256, SMEM_BYTES>>>(xs, out);
}

// round 9
// speedup vs baseline: 1.2390x; 1.0667x over previous
#include <cuda_runtime.h>
#include <cuda_bf16.h>
#include <cstdint>

// out[b,n] = max(0, 1 - sum_k (1 - xs[b,k]) * sigmoid(W[k,n]))
// B=4096, K=1024, N=1024, fp32 in/out.
static constexpr int Bdim = 4096;
static constexpr int Kdim = 1024;
static constexpr int Ndim = 1024;

// Tiled, pre-swizzled operand storage (__device__ globals: allocation-free rule).
// g_A: blocks i = mt*16+kt (mt 0..31, kt 0..15): 128 m-rows x 64 k bf16,
//      128B rows, SW128, 16KB each.
// g_W: blocks j = nt*16+kt (nt 0..7, kt 0..15): 128 n-rows x 64 k bf16 (W^T,
//      n-major), 128B rows, SW128, 16KB each.
__device__ __align__(128) __nv_bfloat16 g_A[(size_t)Bdim * Kdim];
__device__ __align__(128) __nv_bfloat16 g_W[(size_t)Kdim * Ndim];

__device__ __forceinline__ uint32_t swz(uint32_t x) { return x ^ ((x >> 3) & 0x70); }

// ---------------------------------------------------------------------------
// prep_A: (1-x) -> bf16, tiled + SW128 (R6 form, MLP=8). 512 blocks.
// ---------------------------------------------------------------------------
__global__ __launch_bounds__(256) void prep_A_kernel(const float* __restrict__ xs) {
    const int tid = threadIdx.x;
    char* gA = reinterpret_cast<char*>(g_A);
    const float4* src[4];
    size_t dst[4];
    float4 v0[4], v1[4];
    int base = blockIdx.x * 256 + tid;
#pragma unroll
    for (int j = 0; j < 4; j++) {
        int c = base + j * 131072;          // chunk id, 512K total
        int b = c >> 7, k8 = c & 127;
        src[j] = reinterpret_cast<const float4*>(xs + (size_t)b * 1024 + k8 * 8);
        int kt = k8 >> 3, c8 = k8 & 7, mt = b >> 7, r = b & 127;
        dst[j] = (size_t)(mt * 16 + kt) * 16384 + swz((uint32_t)(r * 128 + c8 * 16));
    }
#pragma unroll
    for (int j = 0; j < 4; j++) { v0[j] = src[j][0]; v1[j] = src[j][1]; }
#pragma unroll
    for (int j = 0; j < 4; j++) {
        __nv_bfloat162 p0 = __floats2bfloat162_rn(1.0f - v0[j].x, 1.0f - v0[j].y);
        __nv_bfloat162 p1 = __floats2bfloat162_rn(1.0f - v0[j].z, 1.0f - v0[j].w);
        __nv_bfloat162 p2 = __floats2bfloat162_rn(1.0f - v1[j].x, 1.0f - v1[j].y);
        __nv_bfloat162 p3 = __floats2bfloat162_rn(1.0f - v1[j].z, 1.0f - v1[j].w);
        uint4 u;
        u.x = *reinterpret_cast<uint32_t*>(&p0);
        u.y = *reinterpret_cast<uint32_t*>(&p1);
        u.z = *reinterpret_cast<uint32_t*>(&p2);
        u.w = *reinterpret_cast<uint32_t*>(&p3);
        *reinterpret_cast<uint4*>(gA + dst[j]) = u;
    }
}

// ---------------------------------------------------------------------------
// prep_W: sigmoid + transpose [K,N] -> [N,K] (n-major), tiled + SW128.
// 128 blocks, one per W block (64 k x 128 n fp32 in -> 128 n x 64 k bf16 out).
// ---------------------------------------------------------------------------
__global__ __launch_bounds__(256) void prep_W_kernel(const float* __restrict__ w) {
    __shared__ __nv_bfloat16 ts[128 * 72];   // [n][k], stride 72 (144B rows)
    const int tid = threadIdx.x;
    const int j = blockIdx.x;                // block id = nt*16+kt
    const int nt = j >> 4, kt = j & 15;

#pragma unroll
    for (int q = 0; q < 8; q++) {
        int lin = tid + q * 256;             // 0..2047 float4s (64 k x 32 f4)
        int kl = lin >> 5, nc4 = lin & 31;
        float4 v = *reinterpret_cast<const float4*>(
            w + (size_t)(kt * 64 + kl) * 1024 + nt * 128 + nc4 * 4);
        float s0 = 1.0f / (1.0f + __expf(-v.x));
        float s1 = 1.0f / (1.0f + __expf(-v.y));
        float s2 = 1.0f / (1.0f + __expf(-v.z));
        float s3 = 1.0f / (1.0f + __expf(-v.w));
        ts[(nc4 * 4 + 0) * 72 + kl] = __float2bfloat16_rn(s0);
        ts[(nc4 * 4 + 1) * 72 + kl] = __float2bfloat16_rn(s1);
        ts[(nc4 * 4 + 2) * 72 + kl] = __float2bfloat16_rn(s2);
        ts[(nc4 * 4 + 3) * 72 + kl] = __float2bfloat16_rn(s3);
    }
    __syncthreads();

    char* gW = reinterpret_cast<char*>(g_W);
#pragma unroll
    for (int q = 0; q < 4; q++) {
        int lin = tid + q * 256;             // 0..1023 16B chunks
        int n = lin >> 3, c8 = lin & 7;
        uint4 u = *reinterpret_cast<uint4*>(&ts[n * 72 + c8 * 8]);
        size_t off = (size_t)j * 16384 + swz((uint32_t)(n * 128 + c8 * 16));
        *reinterpret_cast<uint4*>(gW + off) = u;
    }
}

// ---------------------------------------------------------------------------
// GEMM: 128x128 CTA tile, BK=64, 3-stage cp.async.bulk pipeline,
// A: ldmatrix non-trans; B (n-major): ldmatrix non-trans; mma bf16/f32.
// ---------------------------------------------------------------------------
static constexpr int STAGES = 3;
static constexpr int KT = Kdim / 64;                 // 16
static constexpr uint32_t STAGE_B = 32768;           // 16KB A + 16KB B
static constexpr uint32_t BUF_OFF = 128;
static constexpr uint32_t SMEM_BYTES = BUF_OFF + STAGES * STAGE_B;  // 98432

__device__ __forceinline__ void mbar_wait(uint32_t addr, uint32_t parity) {
    asm volatile(
        "{\n\t.reg .pred P;\n"
        "W_%=:\n\t"
        "mbarrier.try_wait.parity.acquire.cta.shared::cta.b64 P, [%0], %1, 0x989680;\n\t"
        "@P bra.uni D_%=;\n\t"
        "bra.uni W_%=;\n"
        "D_%=:\n\t}"
        :: "r"(addr), "r"(parity) : "memory");
}

__global__ __launch_bounds__(256, 2) void fuzzyand_gemm(float* __restrict__ out) {
    extern __shared__ char smem[];
    const uint32_t sb = (uint32_t)__cvta_generic_to_shared(smem);
    const int tid = threadIdx.x;
    const int wid = tid >> 5;
    const int lane = tid & 31;
    const int wm = (wid & 3) * 32;
    const int wn = (wid >> 2) * 64;
    const int bm = blockIdx.y * 128;
    const int bn = blockIdx.x * 128;

    if (tid == 0) {
#pragma unroll
        for (int s = 0; s < STAGES; s++)
            asm volatile("mbarrier.init.shared.b64 [%0], %1;"
                         :: "r"(sb + 8 * s), "r"(1u) : "memory");
    }
    __syncthreads();

    const char* Ab = reinterpret_cast<const char*>(g_A) + (size_t)(blockIdx.y * 16) * 16384;
    const char* Bb = reinterpret_cast<const char*>(g_W) + (size_t)(blockIdx.x * 16) * 16384;

    auto issue = [&](int stage, int kt) {
        uint32_t mb = sb + 8 * stage;
        uint32_t dst = sb + BUF_OFF + stage * STAGE_B;
        asm volatile("mbarrier.arrive.expect_tx.shared.b64 _, [%0], %1;"
                     :: "r"(mb), "r"(STAGE_B) : "memory");
        asm volatile(
            "cp.async.bulk.shared::cluster.global.mbarrier::complete_tx::bytes "
            "[%0], [%1], %2, [%3];"
            :: "r"(dst), "l"(Ab + (size_t)kt * 16384), "r"(16384u), "r"(mb) : "memory");
        asm volatile(
            "cp.async.bulk.shared::cluster.global.mbarrier::complete_tx::bytes "
            "[%0], [%1], %2, [%3];"
            :: "r"(dst + 16384u), "l"(Bb + (size_t)kt * 16384), "r"(16384u), "r"(mb) : "memory");
    };

    if (tid == 0) { issue(0, 0); issue(1, 1); }

    float acc[2][8][4];
#pragma unroll
    for (int mi = 0; mi < 2; mi++)
#pragma unroll
        for (int ni = 0; ni < 8; ni++)
#pragma unroll
            for (int e = 0; e < 4; e++) acc[mi][ni][e] = 0.0f;

    // A addressing (non-trans, m-major rows)
    const uint32_t a_row0 = (uint32_t)(wm + (lane & 15)) * 128;
    const uint32_t a_xor0 = ((wm + (lane & 15)) & 7) << 4;
    const uint32_t a_row1 = (uint32_t)(wm + 16 + (lane & 15)) * 128;
    const uint32_t a_xor1 = ((wm + 16 + (lane & 15)) & 7) << 4;
    const uint32_t a_hi = (uint32_t)((lane >> 4) << 4);
    // B addressing (non-trans, n-major rows): row n = wn + (lane&7) + 8*(lane>>4)
    const uint32_t bl_n  = (uint32_t)(wn + (lane & 7) + 8 * (lane >> 4));
    const uint32_t b_row = bl_n * 128;
    const uint32_t b_xor = (bl_n & 7) << 4;          // invariant under n += 16
    const uint32_t b_bc  = (uint32_t)(((lane >> 3) & 1) << 4);

#pragma unroll 1
    for (int kt = 0; kt < KT; kt++) {
        const int stage = kt % STAGES;
        mbar_wait(sb + 8 * stage, (uint32_t)((kt / STAGES) & 1));

        const uint32_t a_s = sb + BUF_OFF + stage * STAGE_B;
        const uint32_t b_s = a_s + 16384;

#pragma unroll
        for (int ks = 0; ks < 4; ks++) {
            const uint32_t kb = ks * 32;

            uint32_t a[2][4];
            {
                uint32_t bc = kb + a_hi;
                uint32_t ad0 = a_s + ((a_row0 + bc) ^ a_xor0);
                uint32_t ad1 = a_s + ((a_row1 + bc) ^ a_xor1);
                asm volatile(
                    "ldmatrix.sync.aligned.m8n8.x4.shared.b16 {%0,%1,%2,%3}, [%4];"
                    : "=r"(a[0][0]), "=r"(a[0][1]), "=r"(a[0][2]), "=r"(a[0][3])
                    : "r"(ad0));
                asm volatile(
                    "ldmatrix.sync.aligned.m8n8.x4.shared.b16 {%0,%1,%2,%3}, [%4];"
                    : "=r"(a[1][0]), "=r"(a[1][1]), "=r"(a[1][2]), "=r"(a[1][3])
                    : "r"(ad1));
            }

            // B: 4 non-trans x4 ldmatrix, each covers 16 n x 16 k.
            // regs: r0,r1 -> n 0-7 (k 0-7, 8-15); r2,r3 -> n 8-15.
            uint32_t b[4][4];
            {
                uint32_t bc = kb + b_bc;
#pragma unroll
                for (int nc = 0; nc < 4; nc++) {
                    uint32_t ad = b_s + (((b_row + nc * 2048) + bc) ^ b_xor);
                    asm volatile(
                        "ldmatrix.sync.aligned.m8n8.x4.shared.b16 {%0,%1,%2,%3}, [%4];"
                        : "=r"(b[nc][0]), "=r"(b[nc][1]), "=r"(b[nc][2]), "=r"(b[nc][3])
                        : "r"(ad));
                }
            }

#pragma unroll
            for (int mi = 0; mi < 2; mi++)
#pragma unroll
                for (int ni = 0; ni < 8; ni++) {
                    const int nc = ni >> 1, h = (ni & 1) * 2;
                    asm volatile(
                        "mma.sync.aligned.m16n8k16.row.col.f32.bf16.bf16.f32 "
                        "{%0,%1,%2,%3}, {%4,%5,%6,%7}, {%8,%9}, {%0,%1,%2,%3};"
                        : "+f"(acc[mi][ni][0]), "+f"(acc[mi][ni][1]),
                          "+f"(acc[mi][ni][2]), "+f"(acc[mi][ni][3])
                        : "r"(a[mi][0]), "r"(a[mi][1]), "r"(a[mi][2]), "r"(a[mi][3]),
                          "r"(b[nc][h]), "r"(b[nc][h + 1]));
                }
        }

        __syncthreads();
        if (tid == 0 && kt + 2 < KT) issue((kt + 2) % STAGES, kt + 2);
    }

    float* outp = out + (size_t)bm * Ndim + bn;
#pragma unroll
    for (int mi = 0; mi < 2; mi++) {
#pragma unroll
        for (int ni = 0; ni < 8; ni++) {
            int r0 = wm + mi * 16 + (lane >> 2);
            int c0 = wn + ni * 8 + (lane & 3) * 2;
            float2 v0, v1;
            v0.x = fmaxf(0.0f, 1.0f - acc[mi][ni][0]);
            v0.y = fmaxf(0.0f, 1.0f - acc[mi][ni][1]);
            v1.x = fmaxf(0.0f, 1.0f - acc[mi][ni][2]);
            v1.y = fmaxf(0.0f, 1.0f - acc[mi][ni][3]);
            *reinterpret_cast<float2*>(&outp[(size_t)r0 * Ndim + c0])       = v0;
            *reinterpret_cast<float2*>(&outp[(size_t)(r0 + 8) * Ndim + c0]) = v1;
        }
    }
}

// ---------------------------------------------------------------------------
extern "C" void kernel_launch(void* const* d_in, const int* in_sizes, int n_in,
                              void* d_out, int out_size) {
    const float* xs = (const float*)d_in[0];   // [4096,1024] fp32
    const float* w  = (const float*)d_in[1];   // [1024,1024] fp32
    float* out = (float*)d_out;
    (void)in_sizes; (void)n_in; (void)out_size;

    prep_A_kernel<<<512, 256>>>(xs);
    prep_W_kernel<<<128, 256>>>(w);

    cudaFuncSetAttribute(fuzzyand_gemm,
                         cudaFuncAttributeMaxDynamicSharedMemorySize, SMEM_BYTES);
    dim3 grid(Ndim / 128, Bdim / 128);  // (8, 32) = 256 CTAs
    fuzzyand_gemm<<<grid, 256, SMEM_BYTES>>>(out);
}

// round 10
// speedup vs baseline: 1.2869x; 1.0387x over previous
#include <cuda_runtime.h>
#include <cuda_bf16.h>
#include <cstdint>

// out[b,n] = max(0, 1 - sum_k (1 - xs[b,k]) * sigmoid(W[k,n]))
// B=4096, K=1024, N=1024, fp32 in/out.
static constexpr int Bdim = 4096;
static constexpr int Kdim = 1024;
static constexpr int Ndim = 1024;

// Tiled, pre-swizzled operand storage (__device__ globals: allocation-free rule).
// g_A: blocks i = mt*16+kt (mt 0..31, kt 0..15): 128 m-rows x 64 k bf16,
//      128B rows, SW128, 16KB each.
// g_W: blocks j = nt*16+kt (nt 0..7, kt 0..15): two 8KB halves (n 0..63/64..127),
//      each 64 k-rows x 64 n bf16, 128B rows, SW128.
__device__ __align__(128) __nv_bfloat16 g_A[(size_t)Bdim * Kdim];
__device__ __align__(128) __nv_bfloat16 g_W[(size_t)Kdim * Ndim];

__device__ __forceinline__ void mbar_wait(uint32_t addr, uint32_t parity) {
    asm volatile(
        "{\n\t.reg .pred P;\n"
        "W_%=:\n\t"
        "mbarrier.try_wait.parity.acquire.cta.shared::cta.b64 P, [%0], %1, 0x989680;\n\t"
        "@P bra.uni D_%=;\n\t"
        "bra.uni W_%=;\n"
        "D_%=:\n\t}"
        :: "r"(addr), "r"(parity) : "memory");
}

__device__ __forceinline__ void sts128(uint32_t addr, uint32_t x, uint32_t y,
                                       uint32_t z, uint32_t w) {
    asm volatile("st.shared.v4.b32 [%0], {%1,%2,%3,%4};"
                 :: "r"(addr), "r"(x), "r"(y), "r"(z), "r"(w) : "memory");
}

// ---------------------------------------------------------------------------
// TMA-bulk prep: 640 CTAs. CTA c<512: A rows 8c..8c+7 (32KB contiguous in);
// c>=512: W k-rows 8(c-512)..+7. One 32KB bulk-in, convert via LDS/STS into a
// 16KB staging image laid out as 16 x 1KB destination pieces, 16 bulk-outs.
// Removes the 1M-LDG / 0.5M-STG issue floor that pinned prep at ~7.4us.
// ---------------------------------------------------------------------------
static constexpr uint32_t P_IN = 128;          // 32KB fp32 input
static constexpr uint32_t P_ST = P_IN + 32768; // 16KB bf16 staging
static constexpr uint32_t P_SMEM = P_ST + 16384;  // 49280

__global__ __launch_bounds__(256)
void prep_kernel(const float* __restrict__ xs, const float* __restrict__ w) {
    extern __shared__ char ps[];
    const uint32_t sb = (uint32_t)__cvta_generic_to_shared(ps);
    const int tid = threadIdx.x;
    const int c = blockIdx.x;
    const bool isA = (c < 512);

    const char* src = isA
        ? reinterpret_cast<const char*>(xs) + (size_t)c * 32768
        : reinterpret_cast<const char*>(w) + (size_t)(c - 512) * 32768;

    if (tid == 0) {
        asm volatile("mbarrier.init.shared.b64 [%0], %1;" :: "r"(sb), "r"(1u) : "memory");
        asm volatile("mbarrier.arrive.expect_tx.shared.b64 _, [%0], %1;"
                     :: "r"(sb), "r"(32768u) : "memory");
        asm volatile(
            "cp.async.bulk.shared::cluster.global.mbarrier::complete_tx::bytes "
            "[%0], [%1], %2, [%3];"
            :: "r"(sb + P_IN), "l"(src), "r"(32768u), "r"(sb) : "memory");
    }
    __syncthreads();
    mbar_wait(sb, 0u);   // acquire: orders bulk-in before generic LDS reads

    if (isA) {
#pragma unroll
        for (int q = 0; q < 4; q++) {
            int ch = tid + q * 256;                 // 0..1023
            int kt = ch >> 6, lr = (ch >> 3) & 7, c8 = ch & 7;
            const float4* s4 = reinterpret_cast<const float4*>(
                ps + P_IN + lr * 4096 + kt * 256 + c8 * 32);
            float4 v0 = s4[0], v1 = s4[1];
            __nv_bfloat162 p0 = __floats2bfloat162_rn(1.f - v0.x, 1.f - v0.y);
            __nv_bfloat162 p1 = __floats2bfloat162_rn(1.f - v0.z, 1.f - v0.w);
            __nv_bfloat162 p2 = __floats2bfloat162_rn(1.f - v1.x, 1.f - v1.y);
            __nv_bfloat162 p3 = __floats2bfloat162_rn(1.f - v1.z, 1.f - v1.w);
            uint32_t dst = sb + P_ST + kt * 1024 + lr * 128 + ((c8 * 16) ^ (lr << 4));
            sts128(dst, *reinterpret_cast<uint32_t*>(&p0), *reinterpret_cast<uint32_t*>(&p1),
                        *reinterpret_cast<uint32_t*>(&p2), *reinterpret_cast<uint32_t*>(&p3));
        }
    } else {
#pragma unroll
        for (int q = 0; q < 4; q++) {
            int ch = tid + q * 256;                 // 0..1023
            int nt = ch >> 7, h = (ch >> 6) & 1, kl = (ch >> 3) & 7, nl8 = ch & 7;
            const float4* s4 = reinterpret_cast<const float4*>(
                ps + P_IN + kl * 4096 + nt * 512 + h * 256 + nl8 * 32);
            float4 v0 = s4[0], v1 = s4[1];
            float s0 = 1.0f / (1.0f + __expf(-v0.x));
            float s1 = 1.0f / (1.0f + __expf(-v0.y));
            float s2 = 1.0f / (1.0f + __expf(-v0.z));
            float s3 = 1.0f / (1.0f + __expf(-v0.w));
            float s4f = 1.0f / (1.0f + __expf(-v1.x));
            float s5 = 1.0f / (1.0f + __expf(-v1.y));
            float s6 = 1.0f / (1.0f + __expf(-v1.z));
            float s7 = 1.0f / (1.0f + __expf(-v1.w));
            __nv_bfloat162 p0 = __floats2bfloat162_rn(s0, s1);
            __nv_bfloat162 p1 = __floats2bfloat162_rn(s2, s3);
            __nv_bfloat162 p2 = __floats2bfloat162_rn(s4f, s5);
            __nv_bfloat162 p3 = __floats2bfloat162_rn(s6, s7);
            uint32_t dst = sb + P_ST + (nt * 2 + h) * 1024 + kl * 128 + ((nl8 * 16) ^ (kl << 4));
            sts128(dst, *reinterpret_cast<uint32_t*>(&p0), *reinterpret_cast<uint32_t*>(&p1),
                        *reinterpret_cast<uint32_t*>(&p2), *reinterpret_cast<uint32_t*>(&p3));
        }
    }
    __syncthreads();

    if (tid == 0) {
        asm volatile("fence.proxy.async.shared::cta;" ::: "memory");
        if (isA) {
            const int mt = c >> 4;
            const int rloc0 = (c & 15) * 8;
            char* gA = reinterpret_cast<char*>(g_A);
#pragma unroll
            for (int kt = 0; kt < 16; kt++) {
                char* gdst = gA + (size_t)(mt * 16 + kt) * 16384 + rloc0 * 128;
                asm volatile("cp.async.bulk.global.shared::cta.bulk_group [%0], [%1], %2;"
                             :: "l"(gdst), "r"(sb + P_ST + kt * 1024), "r"(1024u) : "memory");
            }
        } else {
            const int cw = c - 512;
            const int kt = cw >> 3;
            const int klr0 = (cw & 7) * 8;
            char* gW = reinterpret_cast<char*>(g_W);
#pragma unroll
            for (int p = 0; p < 16; p++) {
                int nt = p >> 1, h = p & 1;
                char* gdst = gW + (size_t)(nt * 16 + kt) * 16384 + h * 8192 + klr0 * 128;
                asm volatile("cp.async.bulk.global.shared::cta.bulk_group [%0], [%1], %2;"
                             :: "l"(gdst), "r"(sb + P_ST + p * 1024), "r"(1024u) : "memory");
            }
        }
        asm volatile("cp.async.bulk.commit_group;" ::: "memory");
        asm volatile("cp.async.bulk.wait_group 0;" ::: "memory");
    }
}

// ---------------------------------------------------------------------------
// GEMM (R3/R6 winner, unchanged): 128x128 CTA tile, BK=64, 3-stage
// cp.async.bulk pipeline, ldmatrix + mma.sync.m16n8k16 bf16/f32.
// ---------------------------------------------------------------------------
static constexpr int STAGES = 3;
static constexpr int KT = Kdim / 64;                 // 16
static constexpr uint32_t STAGE_B = 32768;           // 16KB A + 16KB B
static constexpr uint32_t BUF_OFF = 128;
static constexpr uint32_t SMEM_BYTES = BUF_OFF + STAGES * STAGE_B;  // 98432

__global__ __launch_bounds__(256, 2) void fuzzyand_gemm(float* __restrict__ out) {
    extern __shared__ char smem[];
    const uint32_t sb = (uint32_t)__cvta_generic_to_shared(smem);
    const int tid = threadIdx.x;
    const int wid = tid >> 5;
    const int lane = tid & 31;
    const int wm = (wid & 3) * 32;
    const int wn = (wid >> 2) * 64;
    const int bm = blockIdx.y * 128;
    const int bn = blockIdx.x * 128;

    if (tid == 0) {
#pragma unroll
        for (int s = 0; s < STAGES; s++)
            asm volatile("mbarrier.init.shared.b64 [%0], %1;"
                         :: "r"(sb + 8 * s), "r"(1u) : "memory");
    }
    __syncthreads();

    const char* Ab = reinterpret_cast<const char*>(g_A) + (size_t)(blockIdx.y * 16) * 16384;
    const char* Bb = reinterpret_cast<const char*>(g_W) + (size_t)(blockIdx.x * 16) * 16384;

    auto issue = [&](int stage, int kt) {
        uint32_t mb = sb + 8 * stage;
        uint32_t dst = sb + BUF_OFF + stage * STAGE_B;
        asm volatile("mbarrier.arrive.expect_tx.shared.b64 _, [%0], %1;"
                     :: "r"(mb), "r"(STAGE_B) : "memory");
        asm volatile(
            "cp.async.bulk.shared::cluster.global.mbarrier::complete_tx::bytes "
            "[%0], [%1], %2, [%3];"
            :: "r"(dst), "l"(Ab + (size_t)kt * 16384), "r"(16384u), "r"(mb) : "memory");
        asm volatile(
            "cp.async.bulk.shared::cluster.global.mbarrier::complete_tx::bytes "
            "[%0], [%1], %2, [%3];"
            :: "r"(dst + 16384u), "l"(Bb + (size_t)kt * 16384), "r"(16384u), "r"(mb) : "memory");
    };

    if (tid == 0) { issue(0, 0); issue(1, 1); }

    float acc[2][8][4];
#pragma unroll
    for (int mi = 0; mi < 2; mi++)
#pragma unroll
        for (int ni = 0; ni < 8; ni++)
#pragma unroll
            for (int e = 0; e < 4; e++) acc[mi][ni][e] = 0.0f;

    const uint32_t a_row0 = (uint32_t)(wm + (lane & 15)) * 128;
    const uint32_t a_xor0 = ((wm + (lane & 15)) & 7) << 4;
    const uint32_t a_row1 = (uint32_t)(wm + 16 + (lane & 15)) * 128;
    const uint32_t a_xor1 = ((wm + 16 + (lane & 15)) & 7) << 4;
    const uint32_t a_hi = (uint32_t)((lane >> 4) << 4);
    const uint32_t b_half = (uint32_t)((wn >> 6) * 8192);
    const uint32_t b_nb = (uint32_t)((wn & 63) * 2 + ((lane >> 4) << 4));

#pragma unroll 1
    for (int kt = 0; kt < KT; kt++) {
        const int stage = kt % STAGES;
        mbar_wait(sb + 8 * stage, (uint32_t)((kt / STAGES) & 1));

        const uint32_t a_s = sb + BUF_OFF + stage * STAGE_B;
        const uint32_t b_s = a_s + 16384;

#pragma unroll
        for (int ks = 0; ks < 4; ks++) {
            const uint32_t kb = ks * 32;

            uint32_t a[2][4];
            {
                uint32_t bc = kb + a_hi;
                uint32_t ad0 = a_s + ((a_row0 + bc) ^ a_xor0);
                uint32_t ad1 = a_s + ((a_row1 + bc) ^ a_xor1);
                asm volatile(
                    "ldmatrix.sync.aligned.m8n8.x4.shared.b16 {%0,%1,%2,%3}, [%4];"
                    : "=r"(a[0][0]), "=r"(a[0][1]), "=r"(a[0][2]), "=r"(a[0][3])
                    : "r"(ad0));
                asm volatile(
                    "ldmatrix.sync.aligned.m8n8.x4.shared.b16 {%0,%1,%2,%3}, [%4];"
                    : "=r"(a[1][0]), "=r"(a[1][1]), "=r"(a[1][2]), "=r"(a[1][3])
                    : "r"(ad1));
            }

            uint32_t b[8][2];
            {
                uint32_t krow = (uint32_t)(ks * 16 + (lane & 15));
                uint32_t base = krow * 128;
                uint32_t kxor = (krow & 7) << 4;
#pragma unroll
                for (int nc = 0; nc < 4; nc++) {
                    uint32_t bc = b_nb + nc * 32;
                    uint32_t ad = b_s + b_half + ((base + bc) ^ kxor);
                    asm volatile(
                        "ldmatrix.sync.aligned.m8n8.x4.trans.shared.b16 {%0,%1,%2,%3}, [%4];"
                        : "=r"(b[2 * nc][0]), "=r"(b[2 * nc][1]),
                          "=r"(b[2 * nc + 1][0]), "=r"(b[2 * nc + 1][1])
                        : "r"(ad));
                }
            }

#pragma unroll
            for (int mi = 0; mi < 2; mi++)
#pragma unroll
                for (int ni = 0; ni < 8; ni++) {
                    asm volatile(
                        "mma.sync.aligned.m16n8k16.row.col.f32.bf16.bf16.f32 "
                        "{%0,%1,%2,%3}, {%4,%5,%6,%7}, {%8,%9}, {%0,%1,%2,%3};"
                        : "+f"(acc[mi][ni][0]), "+f"(acc[mi][ni][1]),
                          "+f"(acc[mi][ni][2]), "+f"(acc[mi][ni][3])
                        : "r"(a[mi][0]), "r"(a[mi][1]), "r"(a[mi][2]), "r"(a[mi][3]),
                          "r"(b[ni][0]), "r"(b[ni][1]));
                }
        }

        __syncthreads();
        if (tid == 0 && kt + 2 < KT) issue((kt + 2) % STAGES, kt + 2);
    }

    float* outp = out + (size_t)bm * Ndim + bn;
#pragma unroll
    for (int mi = 0; mi < 2; mi++) {
#pragma unroll
        for (int ni = 0; ni < 8; ni++) {
            int r0 = wm + mi * 16 + (lane >> 2);
            int c0 = wn + ni * 8 + (lane & 3) * 2;
            float2 v0, v1;
            v0.x = fmaxf(0.0f, 1.0f - acc[mi][ni][0]);
            v0.y = fmaxf(0.0f, 1.0f - acc[mi][ni][1]);
            v1.x = fmaxf(0.0f, 1.0f - acc[mi][ni][2]);
            v1.y = fmaxf(0.0f, 1.0f - acc[mi][ni][3]);
            *reinterpret_cast<float2*>(&outp[(size_t)r0 * Ndim + c0])       = v0;
            *reinterpret_cast<float2*>(&outp[(size_t)(r0 + 8) * Ndim + c0]) = v1;
        }
    }
}

// ---------------------------------------------------------------------------
extern "C" void kernel_launch(void* const* d_in, const int* in_sizes, int n_in,
                              void* d_out, int out_size) {
    const float* xs = (const float*)d_in[0];   // [4096,1024] fp32
    const float* w  = (const float*)d_in[1];   // [1024,1024] fp32
    float* out = (float*)d_out;
    (void)in_sizes; (void)n_in; (void)out_size;

    cudaFuncSetAttribute(prep_kernel,
                         cudaFuncAttributeMaxDynamicSharedMemorySize, P_SMEM);
    prep_kernel<<<640, 256, P_SMEM>>>(xs, w);

    cudaFuncSetAttribute(fuzzyand_gemm,
                         cudaFuncAttributeMaxDynamicSharedMemorySize, SMEM_BYTES);
    dim3 grid(Ndim / 128, Bdim / 128);  // (8, 32) = 256 CTAs
    fuzzyand_gemm<<<grid, 256, SMEM_BYTES>>>(out);
}